// round 8
// baseline (speedup 1.0000x reference)
#include <cuda_runtime.h>
#include <stdint.h>

// KVEmbedding: out[b,l,:] = table[indices[b,l], :]
// indices: int32 [819200], table: float32 [1000000,64], out: float32 [819200,64]
// R3 shape (16 lanes/row float4, MLP=4) + partial L2 pinning at a
// DISCRIMINATING dose: rows idx < 470000 (120.3MB < 126MB L2) read with
// evict_last. If the policy partition is real, cross-replay hit-rate rises
// to ~57% (vs 42% natural) and DRAM reads drop ~35MB/replay.

static constexpr int VOCAB = 1000000;
static constexpr int PIN_ROWS = 470000;    // 470000*256B = 120.3 MB < 126 MB L2
static constexpr int LANES_PER_ROW = 16;   // 64 floats = 16 x float4
static constexpr int THREADS = 256;
static constexpr int ROWS_PER_SLOT = 4;
static constexpr int SLOTS_PER_BLOCK = THREADS / LANES_PER_ROW;        // 16
static constexpr int ROWS_PER_BLOCK = SLOTS_PER_BLOCK * ROWS_PER_SLOT; // 64

__device__ __forceinline__ unsigned clamp_idx(int i) {
    unsigned u = (unsigned)i;
    return u < (unsigned)VOCAB ? u : (unsigned)(VOCAB - 1);
}

// float4 non-coherent load with explicit L2 policy register.
__device__ __forceinline__ float4 ldg_pol(const float4* p, uint64_t pol) {
    float4 v;
    asm volatile("ld.global.nc.L2::cache_hint.v4.f32 {%0,%1,%2,%3}, [%4], %5;"
                 : "=f"(v.x), "=f"(v.y), "=f"(v.z), "=f"(v.w)
                 : "l"(p), "l"(pol));
    return v;
}

__device__ __forceinline__ void stg_cs(float4* p, float4 v) {
    asm volatile("st.global.cs.v4.f32 [%0], {%1,%2,%3,%4};"
                 :: "l"(p), "f"(v.x), "f"(v.y), "f"(v.z), "f"(v.w)
                 : "memory");
}

__global__ __launch_bounds__(THREADS)
void kv_gather_pin470_kernel(const int* __restrict__ indices,
                             const float4* __restrict__ table4,
                             float4* __restrict__ out4,
                             int n_rows) {
    uint64_t pol_keep, pol_stream;
    asm("createpolicy.fractional.L2::evict_last.b64 %0, 1.0;"  : "=l"(pol_keep));
    asm("createpolicy.fractional.L2::evict_first.b64 %0, 1.0;" : "=l"(pol_stream));

    int slot = blockIdx.x * SLOTS_PER_BLOCK + (threadIdx.x >> 4);
    int lane = threadIdx.x & 15;
    int row0 = slot * ROWS_PER_SLOT;
    if (row0 >= n_rows) return;

    if (row0 + ROWS_PER_SLOT <= n_rows) {
        int4 iv = __ldg(reinterpret_cast<const int4*>(indices + row0));

        unsigned i0 = clamp_idx(iv.x), i1 = clamp_idx(iv.y);
        unsigned i2 = clamp_idx(iv.z), i3 = clamp_idx(iv.w);

        uint64_t p0 = i0 < PIN_ROWS ? pol_keep : pol_stream;
        uint64_t p1 = i1 < PIN_ROWS ? pol_keep : pol_stream;
        uint64_t p2 = i2 < PIN_ROWS ? pol_keep : pol_stream;
        uint64_t p3 = i3 < PIN_ROWS ? pol_keep : pol_stream;

        float4 v0 = ldg_pol(&table4[(size_t)i0 * LANES_PER_ROW + lane], p0);
        float4 v1 = ldg_pol(&table4[(size_t)i1 * LANES_PER_ROW + lane], p1);
        float4 v2 = ldg_pol(&table4[(size_t)i2 * LANES_PER_ROW + lane], p2);
        float4 v3 = ldg_pol(&table4[(size_t)i3 * LANES_PER_ROW + lane], p3);

        size_t ob = (size_t)row0 * LANES_PER_ROW + lane;
        stg_cs(&out4[ob + 0 * LANES_PER_ROW], v0);
        stg_cs(&out4[ob + 1 * LANES_PER_ROW], v1);
        stg_cs(&out4[ob + 2 * LANES_PER_ROW], v2);
        stg_cs(&out4[ob + 3 * LANES_PER_ROW], v3);
    } else {
        // Tail (unused for 819200 rows, kept for generality).
        for (int r = row0; r < n_rows; r++) {
            unsigned idx = clamp_idx(__ldg(&indices[r]));
            uint64_t p = idx < PIN_ROWS ? pol_keep : pol_stream;
            float4 v = ldg_pol(&table4[(size_t)idx * LANES_PER_ROW + lane], p);
            stg_cs(&out4[(size_t)r * LANES_PER_ROW + lane], v);
        }
    }
}

extern "C" void kernel_launch(void* const* d_in, const int* in_sizes, int n_in,
                              void* d_out, int out_size) {
    const int*   indices = (const int*)d_in[0];
    const float* table   = (const float*)d_in[1];
    // d_in[2] = dummy, contributes exactly 0 — ignored.

    int n_rows = in_sizes[0];

    dim3 grid((n_rows + ROWS_PER_BLOCK - 1) / ROWS_PER_BLOCK);
    kv_gather_pin470_kernel<<<grid, THREADS>>>(indices,
                                               (const float4*)table,
                                               (float4*)d_out,
                                               n_rows);
}

// round 9
// speedup vs baseline: 1.0331x; 1.0331x over previous
#include <cuda_runtime.h>
#include <stdint.h>

// KVEmbedding: out[b,l,:] = table[indices[b,l], :]
// indices: int32 [819200], table: float32 [1000000,64], out: float32 [819200,64]
// FINAL (R3 shape, best measured): latency-optimal random gather at the
// mixed-stream DRAM roofline (~5.77 TB/s, 72% of spec). 16 threads/row,
// float4 transfers, 4 rows per slot (one int4 index load -> 4 independent
// table LDG.128 in flight), evict-first output stores.
// Established by experiment: MLP>4 neutral, v8 loads regress (2x L1 wavefronts),
// L2 createpolicy pinning ineffective (R6-R8).

static constexpr int VOCAB = 1000000;
static constexpr int LANES_PER_ROW = 16;   // 64 floats = 16 x float4
static constexpr int THREADS = 256;
static constexpr int ROWS_PER_SLOT = 4;    // rows handled per 16-thread slot
static constexpr int SLOTS_PER_BLOCK = THREADS / LANES_PER_ROW;        // 16
static constexpr int ROWS_PER_BLOCK = SLOTS_PER_BLOCK * ROWS_PER_SLOT; // 64

__device__ __forceinline__ unsigned clamp_idx(int i) {
    unsigned u = (unsigned)i;
    return u < (unsigned)VOCAB ? u : (unsigned)(VOCAB - 1);
}

__global__ __launch_bounds__(THREADS)
void kv_gather4_kernel(const int* __restrict__ indices,
                       const float4* __restrict__ table4,
                       float4* __restrict__ out4,
                       int n_rows) {
    int slot = blockIdx.x * SLOTS_PER_BLOCK + (threadIdx.x >> 4);
    int lane = threadIdx.x & 15;
    int row0 = slot * ROWS_PER_SLOT;
    if (row0 >= n_rows) return;

    if (row0 + ROWS_PER_SLOT <= n_rows) {
        // Fast path: one 128-bit index load, 4 independent table loads.
        int4 iv = *reinterpret_cast<const int4*>(indices + row0);
        size_t o0 = (size_t)clamp_idx(iv.x) * LANES_PER_ROW + lane;
        size_t o1 = (size_t)clamp_idx(iv.y) * LANES_PER_ROW + lane;
        size_t o2 = (size_t)clamp_idx(iv.z) * LANES_PER_ROW + lane;
        size_t o3 = (size_t)clamp_idx(iv.w) * LANES_PER_ROW + lane;

        float4 v0 = __ldg(&table4[o0]);
        float4 v1 = __ldg(&table4[o1]);
        float4 v2 = __ldg(&table4[o2]);
        float4 v3 = __ldg(&table4[o3]);

        size_t ob = (size_t)row0 * LANES_PER_ROW + lane;
        __stcs(&out4[ob + 0 * LANES_PER_ROW], v0);
        __stcs(&out4[ob + 1 * LANES_PER_ROW], v1);
        __stcs(&out4[ob + 2 * LANES_PER_ROW], v2);
        __stcs(&out4[ob + 3 * LANES_PER_ROW], v3);
    } else {
        // Tail (unused for 819200 rows, kept for generality).
        for (int r = row0; r < n_rows; r++) {
            unsigned idx = clamp_idx(__ldg(&indices[r]));
            float4 v = __ldg(&table4[(size_t)idx * LANES_PER_ROW + lane]);
            __stcs(&out4[(size_t)r * LANES_PER_ROW + lane], v);
        }
    }
}

extern "C" void kernel_launch(void* const* d_in, const int* in_sizes, int n_in,
                              void* d_out, int out_size) {
    const int*   indices = (const int*)d_in[0];
    const float* table   = (const float*)d_in[1];
    // d_in[2] = dummy, contributes exactly 0 — ignored.

    int n_rows = in_sizes[0];

    dim3 grid((n_rows + ROWS_PER_BLOCK - 1) / ROWS_PER_BLOCK);
    kv_gather4_kernel<<<grid, THREADS>>>(indices,
                                         (const float4*)table,
                                         (float4*)d_out,
                                         n_rows);
}